// round 16
// baseline (speedup 1.0000x reference)
#include <cuda_runtime.h>
#include <cuda_bf16.h>

// ---------------------------------------------------------------------------
// AFNO2D: rfft2(128x128, ortho) -> blockwise complex MLP (8 blocks x 96ch,
// relu, softshrink 0.01) -> irfft2 -> + x.   All tensor-core GEMMs.
//   K1  W-rfft GEMM (scaled 1/128):  Y = G1 . x  -> g_A2  [256 thr, 2 tiles]
//   KMID per (b,wf,n): folded H-DFT (K=128) -> MLP -> folded inv H-DFT
//        G' and W1/W2 time-share one smem region -> 2 CTA/SM
//   K5  W-irfft GEMM: out = G5 . [Zr;Zi] + x              [256 thr, 2 tiles]
// B-fragment loads via ldmatrix.x4 (two n-tiles per instruction).
// ---------------------------------------------------------------------------

#define BB 4
#define HH 128
#define WW 128
#define CH 768
#define NB 8
#define BS 96
#define WF 65
#define MPTS (BB*HH*WF)

__device__ __nv_bfloat162 g_A2[(size_t)MPTS * CH];
__device__ __nv_bfloat162 g_B2[(size_t)MPTS * CH];
__device__ __align__(16) __nv_bfloat16 g_Gp[128 * 136];  // folded H-DFT matrix
__device__ __nv_bfloat16  g_G1[128 * 128];
__device__ __nv_bfloat16  g_G5[128 * 146];
// [layer][ri][n][o*104+i] bf16, pre-transposed, pitch 104
__device__ __align__(16) __nv_bfloat16 g_Wb[2][2][NB][96 * 104];

// ---------------- K0: build matrices + bf16 weights -------------------------
__global__ void k0_build(const float* __restrict__ w1, const float* __restrict__ w2)
{
    int tid = blockIdx.x * 256 + threadIdx.x;
    const int STR = 32 * 256;
    for (int idx = tid; idx < 128 * 136; idx += STR) {
        int hp = idx / 136, k = idx - (idx / 136) * 136;
        float val = 0.0f;
        if (k <= 64) {
            int m = (hp * k) & 127;
            float s, c; sincospif(m * (1.0f / 64.0f), &s, &c);
            val = c;
        } else if (k < 128) {
            int m = (hp * (k - 64)) & 127;
            float s, c; sincospif(m * (1.0f / 64.0f), &s, &c);
            val = s;
        }
        g_Gp[idx] = __float2bfloat16_rn(val);
    }
    for (int idx = tid; idx < 128 * 128; idx += STR) {
        int m = idx >> 7, w = idx & 127;
        float val;
        if (m < 65) {
            int a = (m * w) & 127;
            float s, c; sincospif(a * (1.0f / 64.0f), &s, &c);
            val = c;
        } else {
            int a = ((m - 64) * w) & 127;
            float s, c; sincospif(a * (1.0f / 64.0f), &s, &c);
            val = -s;
        }
        g_G1[idx] = __float2bfloat16_rn(val * 0.0078125f);
    }
    for (int idx = tid; idx < 128 * 146; idx += STR) {
        int w = idx / 146, k = idx - (idx / 146) * 146;
        float val = 0.0f;
        if (k < 65) {
            float eps = (k == 0 || k == 64) ? 1.0f : 2.0f;
            int a = (w * k) & 127;
            float s, c; sincospif(a * (1.0f / 64.0f), &s, &c);
            val = eps * c * (1.0f / 128.0f);
        } else if (k >= 72 && k < 137) {
            int kk = k - 72;
            float eps = (kk == 0 || kk == 64) ? 1.0f : 2.0f;
            int a = (w * kk) & 127;
            float s, c; sincospif(a * (1.0f / 64.0f), &s, &c);
            val = -eps * s * (1.0f / 128.0f);
        }
        g_G5[idx] = __float2bfloat16_rn(val);
    }
    for (int idx = tid; idx < 2 * 2 * NB * 96 * 96; idx += STR) {
        int o = idx % 96;
        int i = (idx / 96) % 96;
        int n = (idx / (96 * 96)) % NB;
        int ri = (idx / (96 * 96 * NB)) % 2;
        int L = idx / (96 * 96 * NB * 2);
        const float* src = L ? w2 : w1;
        float v = src[(((size_t)ri * NB + n) * 96 + i) * 96 + o];
        g_Wb[L][ri][n][o * 104 + i] = __float2bfloat16_rn(v);
    }
}

// ---------------- fragment helpers -----------------------------------------
__device__ __forceinline__ void mma_bf16(float* d, const unsigned* a, unsigned b0, unsigned b1)
{
    asm volatile(
        "mma.sync.aligned.m16n8k16.row.col.f32.bf16.bf16.f32 "
        "{%0,%1,%2,%3},{%4,%5,%6,%7},{%8,%9},{%0,%1,%2,%3};"
        : "+f"(d[0]), "+f"(d[1]), "+f"(d[2]), "+f"(d[3])
        : "r"(a[0]), "r"(a[1]), "r"(a[2]), "r"(a[3]), "r"(b0), "r"(b1));
}
__device__ __forceinline__ unsigned s2u(const void* p)
{
    unsigned r;
    asm("{ .reg .u64 t; cvta.to.shared.u64 t, %1; cvt.u32.u64 %0, t; }" : "=r"(r) : "l"(p));
    return r;
}
__device__ __forceinline__ void ldsm_x4(unsigned* r, unsigned a)
{
    asm volatile("ldmatrix.sync.aligned.m8n8.x4.shared.b16 {%0,%1,%2,%3},[%4];"
                 : "=r"(r[0]), "=r"(r[1]), "=r"(r[2]), "=r"(r[3]) : "r"(a));
}
__device__ __forceinline__ void ldsm_x4t(unsigned* r, unsigned a)
{
    asm volatile("ldmatrix.sync.aligned.m8n8.x4.trans.shared.b16 {%0,%1,%2,%3},[%4];"
                 : "=r"(r[0]), "=r"(r[1]), "=r"(r[2]), "=r"(r[3]) : "r"(a));
}
// A-fragment / trans-B x4 lane offset: rows lane&15, 8-col group lane>>4
#define AOFF(lane, P) ((((lane) & 15) * (P) + (((lane) >> 4) << 3)) * 2)
// non-trans B x4 ([n][k]): matrices (nt0,kh0),(nt0,kh1),(nt1,kh0),(nt1,kh1)
#define B4OFF(lane, P) ((((((lane) >> 4) << 3) + ((lane) & 7)) * (P) + ((((lane) >> 3) & 1) << 3)) * 2)

// ---------------------------------------------------------------------------
// K1: W-rfft as GEMM. 256 threads, 8 warps (4 M x 2 N of 48). 2 bh tiles/CTA.
// ---------------------------------------------------------------------------
#define P1 136
#define PB1 104
#define K1_SG 0
#define K1_SB 34816
#define K1_TOT 61440
#define STG_P 98

__global__ void __launch_bounds__(256) k1g(const float* __restrict__ x)
{
    extern __shared__ char sm[];
    __nv_bfloat16* sG  = (__nv_bfloat16*)(sm + K1_SG);
    __nv_bfloat16* sB  = (__nv_bfloat16*)(sm + K1_SB);
    __nv_bfloat16* stg = (__nv_bfloat16*)(sm + K1_SB);

    const int tid = threadIdx.x;
    const int c0 = blockIdx.x * 96;
    const int lane = tid & 31, warp = tid >> 5;
    const int g = lane >> 2, tig = lane & 3;
    const int wm = warp & 3, wn = warp >> 2;

    {
        const unsigned* src = (const unsigned*)g_G1;
        unsigned* dst = (unsigned*)sG;
        for (int p = tid; p < 128 * 64; p += 256) {
            int row = p >> 6, kp = p & 63;
            dst[row * 68 + kp] = src[p];
        }
    }

    const unsigned sG_u = s2u(sG), sB_u = s2u(sB);
    const unsigned abase   = sG_u + (wm * 32) * P1 * 2 + AOFF(lane, P1);
    const unsigned btbase4 = sB_u + AOFF(lane, PB1) + (wn * 48) * 2;

    for (int t = 0; t < 2; t++) {
        const int bh = blockIdx.y * 2 + t;
        __syncthreads();   // sG ready / previous stg reads done

        {
            const float* px = x + (size_t)bh * WW * CH + c0;
            for (int idx = tid; idx < 128 * 24; idx += 256) {
                int w = idx / 24, c = (idx - (idx / 24) * 24) * 4;
                float4 v = *(const float4*)(px + (size_t)w * CH + c);
                *(__nv_bfloat162*)(sB + w * PB1 + c)     = __floats2bfloat162_rn(v.x, v.y);
                *(__nv_bfloat162*)(sB + w * PB1 + c + 2) = __floats2bfloat162_rn(v.z, v.w);
            }
        }
        __syncthreads();

        float acc[2][6][4];
        #pragma unroll
        for (int mt = 0; mt < 2; mt++)
            #pragma unroll
            for (int nt = 0; nt < 6; nt++)
                #pragma unroll
                for (int r = 0; r < 4; r++) acc[mt][nt][r] = 0.0f;

        #pragma unroll
        for (int ks = 0; ks < 8; ks++) {
            const int k0 = ks * 16;
            unsigned a[2][4];
            ldsm_x4(a[0], abase + k0 * 2);
            ldsm_x4(a[1], abase + (16 * P1 + k0) * 2);
            #pragma unroll
            for (int ntp = 0; ntp < 3; ntp++) {
                unsigned bb[4];
                ldsm_x4t(bb, btbase4 + (k0 * PB1 + ntp * 16) * 2);
                mma_bf16(acc[0][2*ntp],     a[0], bb[0], bb[1]);
                mma_bf16(acc[1][2*ntp],     a[1], bb[0], bb[1]);
                mma_bf16(acc[0][2*ntp + 1], a[0], bb[2], bb[3]);
                mma_bf16(acc[1][2*ntp + 1], a[1], bb[2], bb[3]);
            }
        }
        __syncthreads();   // sB reads done -> stg may overwrite

        #pragma unroll
        for (int mt = 0; mt < 2; mt++)
            #pragma unroll
            for (int nt = 0; nt < 6; nt++) {
                int row0 = wm * 32 + mt * 16 + g;
                int jj = wn * 48 + nt * 8 + 2 * tig;
                *(__nv_bfloat162*)(stg + row0 * STG_P + jj) =
                    __floats2bfloat162_rn(acc[mt][nt][0], acc[mt][nt][1]);
                *(__nv_bfloat162*)(stg + (row0 + 8) * STG_P + jj) =
                    __floats2bfloat162_rn(acc[mt][nt][2], acc[mt][nt][3]);
            }
        __syncthreads();

        {
            __nv_bfloat162* pa = g_A2 + (size_t)bh * WF * CH + c0;
            const __nv_bfloat16 z = __float2bfloat16_rn(0.0f);
            for (int idx = tid; idx < 65 * 96; idx += 256) {
                int k = idx / 96, c = idx - (idx / 96) * 96;
                __nv_bfloat16 re = stg[k * STG_P + c];
                __nv_bfloat16 im = (k >= 1 && k <= 63) ? stg[(64 + k) * STG_P + c] : z;
                pa[(size_t)k * CH + c] = __halves2bfloat162(re, im);
            }
        }
    }
}

// ---------------------------------------------------------------------------
// KMID: folded H-DFT -> MLP -> folded inverse H-DFT. 512 thr, 2 CTA/SM.
// ---------------------------------------------------------------------------
#define GPP 136
#define PBX 104
#define XP  200
#define WP  104
#define SM_W   0
#define SM_WI  19968
#define SM_X   39936
#define SM_B1  93184
#define SM_B2  93952
#define SM_TOT 94720

__global__ void __launch_bounds__(512, 2) kmid(const float* __restrict__ b1,
                                               const float* __restrict__ b2)
{
    extern __shared__ char sm[];
    __nv_bfloat16* sG  = (__nv_bfloat16*)(sm + SM_W);
    __nv_bfloat16* sWr = (__nv_bfloat16*)(sm + SM_W);
    __nv_bfloat16* sWi = (__nv_bfloat16*)(sm + SM_WI);
    __nv_bfloat16* sX  = (__nv_bfloat16*)(sm + SM_X);
    __nv_bfloat16* sXm = (__nv_bfloat16*)(sm + SM_X);
    __nv_bfloat16* sOt = (__nv_bfloat16*)(sm + SM_X);
    __nv_bfloat16* stg = (__nv_bfloat16*)(sm + SM_X);
    float* sB1 = (float*)(sm + SM_B1);
    float* sB2 = (float*)(sm + SM_B2);

    const int tid = threadIdx.x;
    const int n   = blockIdx.x;
    const int b   = blockIdx.y / WF;
    const int wf  = blockIdx.y - b * WF;
    const int lane = tid & 31, warp = tid >> 5;
    const int g = lane >> 2, tig = lane & 3;
    const int wm = warp & 3, wq = warp >> 2;
    const int wn = wq >> 1, wh = wq & 1;

    {
        const uint4* src = (const uint4*)g_Gp;
        uint4* dst = (uint4*)sG;
        for (int p = tid; p < 128 * 136 * 2 / 16; p += 512) dst[p] = src[p];
        if (tid < 192) {
            int half = tid / 96, j = tid - half * 96;
            sB1[tid] = b1[half * (NB * BS) + n * BS + j];
            sB2[tid] = b2[half * (NB * BS) + n * BS + j];
        }
    }
    {
        const __nv_bfloat162* pa = g_A2 + ((size_t)(b * HH) * WF + wf) * CH + n * BS;
        for (int idx = tid; idx < 65 * 48; idx += 512) {
            int h = idx / 48, c = (idx - (idx / 48) * 48) * 2;
            uint2 ua = *(const uint2*)(pa + (size_t)h * WF * CH + c);
            float2 a0 = __bfloat1622float2(*(__nv_bfloat162*)&ua.x);
            float2 a1 = __bfloat1622float2(*(__nv_bfloat162*)&ua.y);
            if (h == 0 || h == 64) {
                *(__nv_bfloat162*)(sX + h * PBX + c)         = __floats2bfloat162_rn(a0.x, a1.x);
                *(__nv_bfloat162*)(sX + (128 + h) * PBX + c) = __floats2bfloat162_rn(a0.y, a1.y);
            } else {
                uint2 ub = *(const uint2*)(pa + (size_t)(128 - h) * WF * CH + c);
                float2 b0 = __bfloat1622float2(*(__nv_bfloat162*)&ub.x);
                float2 b1v = __bfloat1622float2(*(__nv_bfloat162*)&ub.y);
                *(__nv_bfloat162*)(sX + h * PBX + c) =
                    __floats2bfloat162_rn(a0.x + b0.x, a1.x + b1v.x);          // Per
                *(__nv_bfloat162*)(sX + (64 + h) * PBX + c) =
                    __floats2bfloat162_rn(a0.y - b0.y, a1.y - b1v.y);          // Mi
                *(__nv_bfloat162*)(sX + (128 + h) * PBX + c) =
                    __floats2bfloat162_rn(a0.y + b0.y, a1.y + b1v.y);          // Pei
                *(__nv_bfloat162*)(sX + (192 + h) * PBX + c) =
                    __floats2bfloat162_rn(b0.x - a0.x, b1v.x - a1.x);          // -Mr
            }
        }
    }
    __syncthreads();

    const unsigned sG_u = s2u(sG), sX_u = s2u(sX);
    const unsigned sWr_u = s2u(sWr), sWi_u = s2u(sWi);
    const unsigned abaseG  = sG_u + (wm * 32) * GPP * 2 + AOFF(lane, GPP);
    const unsigned abaseX  = sX_u + (wm * 32) * XP * 2 + AOFF(lane, XP);
    const unsigned bplane4 = sX_u + (wn * 128 * PBX + wh * 48) * 2 + AOFF(lane, PBX);
    const unsigned boffW4  = (wh * 48) * WP * 2 + B4OFF(lane, WP);

    float acc[2][6][4];

    // =============== GEMM1: folded forward H-DFT (K=128) ==================
    #pragma unroll
    for (int mt = 0; mt < 2; mt++)
        #pragma unroll
        for (int nt = 0; nt < 6; nt++)
            #pragma unroll
            for (int r = 0; r < 4; r++) acc[mt][nt][r] = 0.0f;

    #pragma unroll
    for (int ks = 0; ks < 8; ks++) {
        const int k0 = ks * 16;
        unsigned a[2][4];
        ldsm_x4(a[0], abaseG + k0 * 2);
        ldsm_x4(a[1], abaseG + (16 * GPP + k0) * 2);
        #pragma unroll
        for (int ntp = 0; ntp < 3; ntp++) {
            unsigned bb[4];
            ldsm_x4t(bb, bplane4 + (k0 * PBX + ntp * 16) * 2);
            mma_bf16(acc[0][2*ntp],     a[0], bb[0], bb[1]);
            mma_bf16(acc[1][2*ntp],     a[1], bb[0], bb[1]);
            mma_bf16(acc[0][2*ntp + 1], a[0], bb[2], bb[3]);
            mma_bf16(acc[1][2*ntp + 1], a[1], bb[2], bb[3]);
        }
    }
    __syncthreads();

    #pragma unroll
    for (int mt = 0; mt < 2; mt++)
        #pragma unroll
        for (int nt = 0; nt < 6; nt++) {
            int row0 = wm * 32 + mt * 16 + g;
            int jj = wq * 48 + nt * 8 + 2 * tig;
            *(__nv_bfloat162*)(sXm + row0 * XP + jj) =
                __floats2bfloat162_rn(acc[mt][nt][0], acc[mt][nt][1]);
            *(__nv_bfloat162*)(sXm + (row0 + 8) * XP + jj) =
                __floats2bfloat162_rn(acc[mt][nt][2], acc[mt][nt][3]);
        }
    {
        const uint4* srcR = (const uint4*)&g_Wb[0][0][n][0];
        const uint4* srcI = (const uint4*)&g_Wb[0][1][n][0];
        uint4* dR = (uint4*)sWr;
        uint4* dI = (uint4*)sWi;
        for (int p = tid; p < 96 * 104 / 8; p += 512) { dR[p] = srcR[p]; dI[p] = srcI[p]; }
    }
    __syncthreads();

    // =============== MLP layer 1 ==========================================
    #pragma unroll
    for (int mt = 0; mt < 2; mt++)
        #pragma unroll
        for (int nt = 0; nt < 6; nt++)
            #pragma unroll
            for (int r = 0; r < 4; r++) acc[mt][nt][r] = 0.0f;

    #pragma unroll
    for (int ks = 0; ks < 12; ks++) {
        const int khalf = (ks >= 6);
        const int k0 = ks * 16, kkm = k0 - khalf * 96;
        const unsigned sW_u = (wn == 0) ? (khalf ? sWi_u : sWr_u)
                                        : (khalf ? sWr_u : sWi_u);
        const unsigned amsk = ((wn == 0) && khalf) ? 0x80008000u : 0u;
        unsigned a[2][4];
        ldsm_x4(a[0], abaseX + k0 * 2);
        ldsm_x4(a[1], abaseX + (16 * XP + k0) * 2);
        if (amsk) {
            #pragma unroll
            for (int mt = 0; mt < 2; mt++)
                #pragma unroll
                for (int r = 0; r < 4; r++) a[mt][r] ^= amsk;
        }
        #pragma unroll
        for (int ntp = 0; ntp < 3; ntp++) {
            unsigned bb[4];
            ldsm_x4(bb, sW_u + boffW4 + (ntp * 16 * WP + kkm) * 2);
            mma_bf16(acc[0][2*ntp],     a[0], bb[0], bb[1]);
            mma_bf16(acc[1][2*ntp],     a[1], bb[0], bb[1]);
            mma_bf16(acc[0][2*ntp + 1], a[0], bb[2], bb[3]);
            mma_bf16(acc[1][2*ntp + 1], a[1], bb[2], bb[3]);
        }
    }
    __syncthreads();

    #pragma unroll
    for (int mt = 0; mt < 2; mt++)
        #pragma unroll
        for (int nt = 0; nt < 6; nt++) {
            int row0 = wm * 32 + mt * 16 + g;
            int jj = wq * 48 + nt * 8 + 2 * tig;
            float bb0 = sB1[jj], bb1 = sB1[jj + 1];
            *(__nv_bfloat162*)(sXm + row0 * XP + jj) = __floats2bfloat162_rn(
                fmaxf(acc[mt][nt][0] + bb0, 0.0f), fmaxf(acc[mt][nt][1] + bb1, 0.0f));
            *(__nv_bfloat162*)(sXm + (row0 + 8) * XP + jj) = __floats2bfloat162_rn(
                fmaxf(acc[mt][nt][2] + bb0, 0.0f), fmaxf(acc[mt][nt][3] + bb1, 0.0f));
        }
    {
        const uint4* srcR = (const uint4*)&g_Wb[1][0][n][0];
        const uint4* srcI = (const uint4*)&g_Wb[1][1][n][0];
        uint4* dR = (uint4*)sWr;
        uint4* dI = (uint4*)sWi;
        for (int p = tid; p < 96 * 104 / 8; p += 512) { dR[p] = srcR[p]; dI[p] = srcI[p]; }
    }
    __syncthreads();

    // =============== MLP layer 2 ==========================================
    #pragma unroll
    for (int mt = 0; mt < 2; mt++)
        #pragma unroll
        for (int nt = 0; nt < 6; nt++)
            #pragma unroll
            for (int r = 0; r < 4; r++) acc[mt][nt][r] = 0.0f;

    #pragma unroll
    for (int ks = 0; ks < 12; ks++) {
        const int khalf = (ks >= 6);
        const int k0 = ks * 16, kkm = k0 - khalf * 96;
        const unsigned sW_u = (wn == 0) ? (khalf ? sWi_u : sWr_u)
                                        : (khalf ? sWr_u : sWi_u);
        const unsigned amsk = ((wn == 0) && khalf) ? 0x80008000u : 0u;
        unsigned a[2][4];
        ldsm_x4(a[0], abaseX + k0 * 2);
        ldsm_x4(a[1], abaseX + (16 * XP + k0) * 2);
        if (amsk) {
            #pragma unroll
            for (int mt = 0; mt < 2; mt++)
                #pragma unroll
                for (int r = 0; r < 4; r++) a[mt][r] ^= amsk;
        }
        #pragma unroll
        for (int ntp = 0; ntp < 3; ntp++) {
            unsigned bb[4];
            ldsm_x4(bb, sW_u + boffW4 + (ntp * 16 * WP + kkm) * 2);
            mma_bf16(acc[0][2*ntp],     a[0], bb[0], bb[1]);
            mma_bf16(acc[1][2*ntp],     a[1], bb[0], bb[1]);
            mma_bf16(acc[0][2*ntp + 1], a[0], bb[2], bb[3]);
            mma_bf16(acc[1][2*ntp + 1], a[1], bb[2], bb[3]);
        }
    }
    __syncthreads();

    // softshrink -> sOt natural [k-stack 256][c] ; G' reload over W
    {
        const float lam = 0.01f;
        #pragma unroll
        for (int mt = 0; mt < 2; mt++)
            #pragma unroll
            for (int nt = 0; nt < 6; nt++) {
                int row0 = wm * 32 + mt * 16 + g;
                int c = wh * 48 + nt * 8 + 2 * tig;
                int jj = wn * 96 + c;
                float bb0 = sB2[jj], bb1 = sB2[jj + 1];
                #pragma unroll
                for (int r = 0; r < 4; r++) {
                    float v = acc[mt][nt][r] + ((r & 1) ? bb1 : bb0);
                    v = copysignf(fmaxf(fabsf(v) - lam, 0.0f), v);
                    int cc = c + (r & 1);
                    int kb = wn * 128 + row0 + (r >> 1) * 8;
                    sOt[kb * PBX + cc] = __float2bfloat16_rn(v);
                }
            }
    }
    {
        const uint4* src = (const uint4*)g_Gp;
        uint4* dst = (uint4*)sG;
        for (int p = tid; p < 128 * 136 * 2 / 16; p += 512) dst[p] = src[p];
    }
    __syncthreads();

    // ======= in-place inverse fold (sync-free: closed {m,64-m} groups) =====
    // POr[m]=Or[m]+Or[128-m]; -MOi[m]=Oi[128-m]-Oi[m];
    // POi[m]=Oi[m]+Oi[128-m]; MOr[m]=Or[m]-Or[128-m]   (m=1..63)
    {
        for (int idx = tid; idx < 32 * 48; idx += 512) {
            int m = idx / 48 + 1;                         // 1..32
            int c = (idx - (idx / 48) * 48) * 2;
            int nn = 64 - m;
            float2 am = __bfloat1622float2(*(__nv_bfloat162*)(sOt + m * PBX + c));
            float2 bm = __bfloat1622float2(*(__nv_bfloat162*)(sOt + (128 - m) * PBX + c));
            float2 cm = __bfloat1622float2(*(__nv_bfloat162*)(sOt + (128 + m) * PBX + c));
            float2 dm = __bfloat1622float2(*(__nv_bfloat162*)(sOt + (256 - m) * PBX + c));
            float2 an, bn, cn, dn;
            if (m != 32) {
                an = __bfloat1622float2(*(__nv_bfloat162*)(sOt + nn * PBX + c));
                bn = __bfloat1622float2(*(__nv_bfloat162*)(sOt + (128 - nn) * PBX + c));
                cn = __bfloat1622float2(*(__nv_bfloat162*)(sOt + (128 + nn) * PBX + c));
                dn = __bfloat1622float2(*(__nv_bfloat162*)(sOt + (256 - nn) * PBX + c));
            }
            *(__nv_bfloat162*)(sOt + m * PBX + c) =
                __floats2bfloat162_rn(am.x + bm.x, am.y + bm.y);
            *(__nv_bfloat162*)(sOt + (64 + m) * PBX + c) =
                __floats2bfloat162_rn(dm.x - cm.x, dm.y - cm.y);
            *(__nv_bfloat162*)(sOt + (128 + m) * PBX + c) =
                __floats2bfloat162_rn(cm.x + dm.x, cm.y + dm.y);
            *(__nv_bfloat162*)(sOt + (192 + m) * PBX + c) =
                __floats2bfloat162_rn(am.x - bm.x, am.y - bm.y);
            if (m != 32) {
                *(__nv_bfloat162*)(sOt + nn * PBX + c) =
                    __floats2bfloat162_rn(an.x + bn.x, an.y + bn.y);
                *(__nv_bfloat162*)(sOt + (64 + nn) * PBX + c) =
                    __floats2bfloat162_rn(dn.x - cn.x, dn.y - cn.y);
                *(__nv_bfloat162*)(sOt + (128 + nn) * PBX + c) =
                    __floats2bfloat162_rn(cn.x + dn.x, cn.y + dn.y);
                *(__nv_bfloat162*)(sOt + (192 + nn) * PBX + c) =
                    __floats2bfloat162_rn(an.x - bn.x, an.y - bn.y);
            }
        }
    }
    __syncthreads();

    // =============== GEMM2: folded inverse H-DFT (K=128) ==================
    #pragma unroll
    for (int mt = 0; mt < 2; mt++)
        #pragma unroll
        for (int nt = 0; nt < 6; nt++)
            #pragma unroll
            for (int r = 0; r < 4; r++) acc[mt][nt][r] = 0.0f;

    #pragma unroll
    for (int ks = 0; ks < 8; ks++) {
        const int k0 = ks * 16;
        unsigned a[2][4];
        ldsm_x4(a[0], abaseG + k0 * 2);
        ldsm_x4(a[1], abaseG + (16 * GPP + k0) * 2);
        #pragma unroll
        for (int ntp = 0; ntp < 3; ntp++) {
            unsigned bb[4];
            ldsm_x4t(bb, bplane4 + (k0 * PBX + ntp * 16) * 2);
            mma_bf16(acc[0][2*ntp],     a[0], bb[0], bb[1]);
            mma_bf16(acc[1][2*ntp],     a[1], bb[0], bb[1]);
            mma_bf16(acc[0][2*ntp + 1], a[0], bb[2], bb[3]);
            mma_bf16(acc[1][2*ntp + 1], a[1], bb[2], bb[3]);
        }
    }
    __syncthreads();

    #pragma unroll
    for (int mt = 0; mt < 2; mt++)
        #pragma unroll
        for (int nt = 0; nt < 6; nt++) {
            int row0 = wm * 32 + mt * 16 + g;
            int jj = wq * 48 + nt * 8 + 2 * tig;
            *(__nv_bfloat162*)(stg + row0 * XP + jj) =
                __floats2bfloat162_rn(acc[mt][nt][0], acc[mt][nt][1]);
            *(__nv_bfloat162*)(stg + (row0 + 8) * XP + jj) =
                __floats2bfloat162_rn(acc[mt][nt][2], acc[mt][nt][3]);
        }
    __syncthreads();

    {
        __nv_bfloat162* pb = g_B2 + ((size_t)(b * HH) * WF + wf) * CH + n * BS;
        for (int idx = tid; idx < HH * BS; idx += 512) {
            int h = idx / BS, c = idx - (idx / BS) * BS;
            pb[(size_t)h * WF * CH + c] =
                __halves2bfloat162(stg[h * XP + c], stg[h * XP + 96 + c]);
        }
    }
}

// ---------------------------------------------------------------------------
// K5: W-irfft as GEMM + residual. 256 threads, 8 warps. 2 bh tiles/CTA.
// ---------------------------------------------------------------------------
#define P5 152
#define PB5 104
#define K5_SG 0
#define K5_SB 38912
#define K5_TOT 68864

__global__ void __launch_bounds__(256) k5g(const float* __restrict__ x,
                                           float* __restrict__ out)
{
    extern __shared__ char sm[];
    __nv_bfloat16* sG = (__nv_bfloat16*)(sm + K5_SG);
    __nv_bfloat16* sB = (__nv_bfloat16*)(sm + K5_SB);

    const int tid = threadIdx.x;
    const int c0 = blockIdx.x * 96;
    const int lane = tid & 31, warp = tid >> 5;
    const int g = lane >> 2, tig = lane & 3;
    const int wm = warp & 3, wn = warp >> 2;

    {
        const unsigned* src = (const unsigned*)g_G5;
        unsigned* dst = (unsigned*)sG;
        for (int p = tid; p < 128 * 73; p += 256) {
            int row = p / 73, c = p - row * 73;
            dst[row * 76 + c] = src[p];
        }
    }
    {
        unsigned* dz = (unsigned*)sB;
        for (int p = tid; p < 144 * 52; p += 256) dz[p] = 0u;
    }

    const unsigned sG_u = s2u(sG), sB_u = s2u(sB);
    const unsigned abase   = sG_u + (wm * 32) * P5 * 2 + AOFF(lane, P5);
    const unsigned btbase4 = sB_u + AOFF(lane, PB5) + (wn * 48) * 2;

    for (int t = 0; t < 2; t++) {
        const int bh = blockIdx.y * 2 + t;
        __syncthreads();   // sG/zero ready; previous GEMM reads done

        {
            const __nv_bfloat162* pb = g_B2 + (size_t)bh * WF * CH + c0;
            for (int idx = tid; idx < 65 * 48; idx += 256) {
                int k = idx / 48, c = (idx - (idx / 48) * 48) * 2;
                uint2 v2 = *(const uint2*)(pb + (size_t)k * CH + c);
                __nv_bfloat162 va = *(__nv_bfloat162*)&v2.x;
                __nv_bfloat162 vb = *(__nv_bfloat162*)&v2.y;
                *(__nv_bfloat162*)(sB + k * PB5 + c) =
                    __halves2bfloat162(__low2bfloat16(va), __low2bfloat16(vb));
                *(__nv_bfloat162*)(sB + (72 + k) * PB5 + c) =
                    __halves2bfloat162(__high2bfloat16(va), __high2bfloat16(vb));
            }
        }
        __syncthreads();

        float acc[2][6][4];
        #pragma unroll
        for (int mt = 0; mt < 2; mt++)
            #pragma unroll
            for (int nt = 0; nt < 6; nt++)
                #pragma unroll
                for (int r = 0; r < 4; r++) acc[mt][nt][r] = 0.0f;

        #pragma unroll
        for (int ks = 0; ks < 9; ks++) {
            const int k0 = ks * 16;
            unsigned a[2][4];
            ldsm_x4(a[0], abase + k0 * 2);
            ldsm_x4(a[1], abase + (16 * P5 + k0) * 2);
            #pragma unroll
            for (int ntp = 0; ntp < 3; ntp++) {
                unsigned bb[4];
                ldsm_x4t(bb, btbase4 + (k0 * PB5 + ntp * 16) * 2);
                mma_bf16(acc[0][2*ntp],     a[0], bb[0], bb[1]);
                mma_bf16(acc[1][2*ntp],     a[1], bb[0], bb[1]);
                mma_bf16(acc[0][2*ntp + 1], a[0], bb[2], bb[3]);
                mma_bf16(acc[1][2*ntp + 1], a[1], bb[2], bb[3]);
            }
        }

        {
            const float* px = x   + (size_t)bh * WW * CH + c0;
            float*       po = out + (size_t)bh * WW * CH + c0;
            #pragma unroll
            for (int mt = 0; mt < 2; mt++)
                #pragma unroll
                for (int nt = 0; nt < 6; nt++) {
                    int row0 = wm * 32 + mt * 16 + g;
                    int jj = wn * 48 + nt * 8 + 2 * tig;
                    float2 xv0 = *(const float2*)(px + (size_t)row0 * CH + jj);
                    float2 xv1 = *(const float2*)(px + (size_t)(row0 + 8) * CH + jj);
                    *(float2*)(po + (size_t)row0 * CH + jj) =
                        make_float2(acc[mt][nt][0] + xv0.x, acc[mt][nt][1] + xv0.y);
                    *(float2*)(po + (size_t)(row0 + 8) * CH + jj) =
                        make_float2(acc[mt][nt][2] + xv1.x, acc[mt][nt][3] + xv1.y);
                }
        }
    }
}

// ---------------------------------------------------------------------------
extern "C" void kernel_launch(void* const* d_in, const int* in_sizes, int n_in,
                              void* d_out, int out_size)
{
    (void)in_sizes; (void)n_in; (void)out_size;
    const float* x  = (const float*)d_in[0];
    const float* w1 = (const float*)d_in[1];
    const float* b1 = (const float*)d_in[2];
    const float* w2 = (const float*)d_in[3];
    const float* b2 = (const float*)d_in[4];
    float* out = (float*)d_out;

    cudaFuncSetAttribute(k1g,  cudaFuncAttributeMaxDynamicSharedMemorySize, K1_TOT);
    cudaFuncSetAttribute(kmid, cudaFuncAttributeMaxDynamicSharedMemorySize, SM_TOT);
    cudaFuncSetAttribute(k5g,  cudaFuncAttributeMaxDynamicSharedMemorySize, K5_TOT);

    k0_build<<<32, 256>>>(w1, w2);
    k1g <<<dim3(CH / 96, BB * HH / 2), 256, K1_TOT>>>(x);
    kmid<<<dim3(NB, BB * WF), 512, SM_TOT>>>(b1, b2);
    k5g <<<dim3(CH / 96, BB * HH / 2), 256, K5_TOT>>>(x, out);
}

// round 17
// speedup vs baseline: 1.0790x; 1.0790x over previous
#include <cuda_runtime.h>
#include <cuda_bf16.h>

// ---------------------------------------------------------------------------
// AFNO2D: rfft2(128x128, ortho) -> blockwise complex MLP (8 blocks x 96ch,
// relu, softshrink 0.01) -> irfft2 -> + x.   All tensor-core GEMMs.
//   K1  W-rfft GEMM (scaled 1/128):  Y = G1 . x  -> g_A2  [x4 ldsm, 2 tiles]
//   KMID per (b,wf,n): folded H-DFT (K=128) -> MLP -> folded inv H-DFT
//        (R13 configuration: x2 ldsm, two-phase fold, 2 CTA/SM)
//   K5  W-irfft GEMM: out = G5 . [Zr;Zi] + x              [x4 ldsm, 2 tiles]
// ---------------------------------------------------------------------------

#define BB 4
#define HH 128
#define WW 128
#define CH 768
#define NB 8
#define BS 96
#define WF 65
#define MPTS (BB*HH*WF)

__device__ __nv_bfloat162 g_A2[(size_t)MPTS * CH];
__device__ __nv_bfloat162 g_B2[(size_t)MPTS * CH];
__device__ __align__(16) __nv_bfloat16 g_Gp[128 * 136];  // folded H-DFT matrix
__device__ __nv_bfloat16  g_G1[128 * 128];
__device__ __nv_bfloat16  g_G5[128 * 146];
// [layer][ri][n][o*104+i] bf16, pre-transposed, pitch 104
__device__ __align__(16) __nv_bfloat16 g_Wb[2][2][NB][96 * 104];

// ---------------- K0: build matrices + bf16 weights -------------------------
__global__ void k0_build(const float* __restrict__ w1, const float* __restrict__ w2)
{
    int tid = blockIdx.x * 256 + threadIdx.x;
    const int STR = 32 * 256;
    for (int idx = tid; idx < 128 * 136; idx += STR) {
        int hp = idx / 136, k = idx - (idx / 136) * 136;
        float val = 0.0f;
        if (k <= 64) {
            int m = (hp * k) & 127;
            float s, c; sincospif(m * (1.0f / 64.0f), &s, &c);
            val = c;
        } else if (k < 128) {
            int m = (hp * (k - 64)) & 127;
            float s, c; sincospif(m * (1.0f / 64.0f), &s, &c);
            val = s;
        }
        g_Gp[idx] = __float2bfloat16_rn(val);
    }
    for (int idx = tid; idx < 128 * 128; idx += STR) {
        int m = idx >> 7, w = idx & 127;
        float val;
        if (m < 65) {
            int a = (m * w) & 127;
            float s, c; sincospif(a * (1.0f / 64.0f), &s, &c);
            val = c;
        } else {
            int a = ((m - 64) * w) & 127;
            float s, c; sincospif(a * (1.0f / 64.0f), &s, &c);
            val = -s;
        }
        g_G1[idx] = __float2bfloat16_rn(val * 0.0078125f);
    }
    for (int idx = tid; idx < 128 * 146; idx += STR) {
        int w = idx / 146, k = idx - (idx / 146) * 146;
        float val = 0.0f;
        if (k < 65) {
            float eps = (k == 0 || k == 64) ? 1.0f : 2.0f;
            int a = (w * k) & 127;
            float s, c; sincospif(a * (1.0f / 64.0f), &s, &c);
            val = eps * c * (1.0f / 128.0f);
        } else if (k >= 72 && k < 137) {
            int kk = k - 72;
            float eps = (kk == 0 || kk == 64) ? 1.0f : 2.0f;
            int a = (w * kk) & 127;
            float s, c; sincospif(a * (1.0f / 64.0f), &s, &c);
            val = -eps * s * (1.0f / 128.0f);
        }
        g_G5[idx] = __float2bfloat16_rn(val);
    }
    for (int idx = tid; idx < 2 * 2 * NB * 96 * 96; idx += STR) {
        int o = idx % 96;
        int i = (idx / 96) % 96;
        int n = (idx / (96 * 96)) % NB;
        int ri = (idx / (96 * 96 * NB)) % 2;
        int L = idx / (96 * 96 * NB * 2);
        const float* src = L ? w2 : w1;
        float v = src[(((size_t)ri * NB + n) * 96 + i) * 96 + o];
        g_Wb[L][ri][n][o * 104 + i] = __float2bfloat16_rn(v);
    }
}

// ---------------- fragment helpers -----------------------------------------
__device__ __forceinline__ void mma_bf16(float* d, const unsigned* a, unsigned b0, unsigned b1)
{
    asm volatile(
        "mma.sync.aligned.m16n8k16.row.col.f32.bf16.bf16.f32 "
        "{%0,%1,%2,%3},{%4,%5,%6,%7},{%8,%9},{%0,%1,%2,%3};"
        : "+f"(d[0]), "+f"(d[1]), "+f"(d[2]), "+f"(d[3])
        : "r"(a[0]), "r"(a[1]), "r"(a[2]), "r"(a[3]), "r"(b0), "r"(b1));
}
__device__ __forceinline__ unsigned s2u(const void* p)
{
    unsigned r;
    asm("{ .reg .u64 t; cvta.to.shared.u64 t, %1; cvt.u32.u64 %0, t; }" : "=r"(r) : "l"(p));
    return r;
}
__device__ __forceinline__ void ldsm_x4(unsigned* r, unsigned a)
{
    asm volatile("ldmatrix.sync.aligned.m8n8.x4.shared.b16 {%0,%1,%2,%3},[%4];"
                 : "=r"(r[0]), "=r"(r[1]), "=r"(r[2]), "=r"(r[3]) : "r"(a));
}
__device__ __forceinline__ void ldsm_x4t(unsigned* r, unsigned a)
{
    asm volatile("ldmatrix.sync.aligned.m8n8.x4.trans.shared.b16 {%0,%1,%2,%3},[%4];"
                 : "=r"(r[0]), "=r"(r[1]), "=r"(r[2]), "=r"(r[3]) : "r"(a));
}
__device__ __forceinline__ void ldsm_x2(unsigned* r, unsigned a)
{
    asm volatile("ldmatrix.sync.aligned.m8n8.x2.shared.b16 {%0,%1},[%2];"
                 : "=r"(r[0]), "=r"(r[1]) : "r"(a));
}
__device__ __forceinline__ void ldsm_x2t(unsigned* r, unsigned a)
{
    asm volatile("ldmatrix.sync.aligned.m8n8.x2.trans.shared.b16 {%0,%1},[%2];"
                 : "=r"(r[0]), "=r"(r[1]) : "r"(a));
}
#define AOFF(lane, P) ((((lane) & 15) * (P) + (((lane) >> 4) << 3)) * 2)
#define BOFF(lane, P) (((((lane) & 15) & 7) * (P) + (((((lane) & 15) >> 3) & 1) << 3)) * 2)
#define BTOFF(lane, P) (((lane) & 15) * (P) * 2)

// ---------------------------------------------------------------------------
// K1: W-rfft as GEMM. 256 threads, 8 warps (4 M x 2 N of 48). 2 bh tiles/CTA.
// B loads via ldsm.x4.trans.
// ---------------------------------------------------------------------------
#define P1 136
#define PB1 104
#define K1_SG 0
#define K1_SB 34816
#define K1_TOT 61440
#define STG_P 98

__global__ void __launch_bounds__(256) k1g(const float* __restrict__ x)
{
    extern __shared__ char sm[];
    __nv_bfloat16* sG  = (__nv_bfloat16*)(sm + K1_SG);
    __nv_bfloat16* sB  = (__nv_bfloat16*)(sm + K1_SB);
    __nv_bfloat16* stg = (__nv_bfloat16*)(sm + K1_SB);

    const int tid = threadIdx.x;
    const int c0 = blockIdx.x * 96;
    const int lane = tid & 31, warp = tid >> 5;
    const int g = lane >> 2, tig = lane & 3;
    const int wm = warp & 3, wn = warp >> 2;

    {
        const unsigned* src = (const unsigned*)g_G1;
        unsigned* dst = (unsigned*)sG;
        for (int p = tid; p < 128 * 64; p += 256) {
            int row = p >> 6, kp = p & 63;
            dst[row * 68 + kp] = src[p];
        }
    }

    const unsigned sG_u = s2u(sG), sB_u = s2u(sB);
    const unsigned abase   = sG_u + (wm * 32) * P1 * 2 + AOFF(lane, P1);
    const unsigned btbase4 = sB_u + AOFF(lane, PB1) + (wn * 48) * 2;

    for (int t = 0; t < 2; t++) {
        const int bh = blockIdx.y * 2 + t;
        __syncthreads();

        {
            const float* px = x + (size_t)bh * WW * CH + c0;
            for (int idx = tid; idx < 128 * 24; idx += 256) {
                int w = idx / 24, c = (idx - (idx / 24) * 24) * 4;
                float4 v = *(const float4*)(px + (size_t)w * CH + c);
                *(__nv_bfloat162*)(sB + w * PB1 + c)     = __floats2bfloat162_rn(v.x, v.y);
                *(__nv_bfloat162*)(sB + w * PB1 + c + 2) = __floats2bfloat162_rn(v.z, v.w);
            }
        }
        __syncthreads();

        float acc[2][6][4];
        #pragma unroll
        for (int mt = 0; mt < 2; mt++)
            #pragma unroll
            for (int nt = 0; nt < 6; nt++)
                #pragma unroll
                for (int r = 0; r < 4; r++) acc[mt][nt][r] = 0.0f;

        #pragma unroll
        for (int ks = 0; ks < 8; ks++) {
            const int k0 = ks * 16;
            unsigned a[2][4];
            ldsm_x4(a[0], abase + k0 * 2);
            ldsm_x4(a[1], abase + (16 * P1 + k0) * 2);
            #pragma unroll
            for (int ntp = 0; ntp < 3; ntp++) {
                unsigned bb[4];
                ldsm_x4t(bb, btbase4 + (k0 * PB1 + ntp * 16) * 2);
                mma_bf16(acc[0][2*ntp],     a[0], bb[0], bb[1]);
                mma_bf16(acc[1][2*ntp],     a[1], bb[0], bb[1]);
                mma_bf16(acc[0][2*ntp + 1], a[0], bb[2], bb[3]);
                mma_bf16(acc[1][2*ntp + 1], a[1], bb[2], bb[3]);
            }
        }
        __syncthreads();

        #pragma unroll
        for (int mt = 0; mt < 2; mt++)
            #pragma unroll
            for (int nt = 0; nt < 6; nt++) {
                int row0 = wm * 32 + mt * 16 + g;
                int jj = wn * 48 + nt * 8 + 2 * tig;
                *(__nv_bfloat162*)(stg + row0 * STG_P + jj) =
                    __floats2bfloat162_rn(acc[mt][nt][0], acc[mt][nt][1]);
                *(__nv_bfloat162*)(stg + (row0 + 8) * STG_P + jj) =
                    __floats2bfloat162_rn(acc[mt][nt][2], acc[mt][nt][3]);
            }
        __syncthreads();

        {
            __nv_bfloat162* pa = g_A2 + (size_t)bh * WF * CH + c0;
            const __nv_bfloat16 z = __float2bfloat16_rn(0.0f);
            for (int idx = tid; idx < 65 * 96; idx += 256) {
                int k = idx / 96, c = idx - (idx / 96) * 96;
                __nv_bfloat16 re = stg[k * STG_P + c];
                __nv_bfloat16 im = (k >= 1 && k <= 63) ? stg[(64 + k) * STG_P + c] : z;
                pa[(size_t)k * CH + c] = __halves2bfloat162(re, im);
            }
        }
    }
}

// ---------------------------------------------------------------------------
// KMID: folded H-DFT -> MLP -> folded inverse H-DFT. 512 thr, 2 CTA/SM.
// (exact R13 configuration)
// ---------------------------------------------------------------------------
#define GPP 136
#define PBX 104
#define XP  200
#define WP  104
#define SM_W   0
#define SM_WI  19968
#define SM_X   39936
#define SM_B1  93184
#define SM_B2  93952
#define SM_TOT 94720

__global__ void __launch_bounds__(512, 2) kmid(const float* __restrict__ b1,
                                               const float* __restrict__ b2)
{
    extern __shared__ char sm[];
    __nv_bfloat16* sG  = (__nv_bfloat16*)(sm + SM_W);
    __nv_bfloat16* sWr = (__nv_bfloat16*)(sm + SM_W);
    __nv_bfloat16* sWi = (__nv_bfloat16*)(sm + SM_WI);
    __nv_bfloat16* sX  = (__nv_bfloat16*)(sm + SM_X);
    __nv_bfloat16* sXm = (__nv_bfloat16*)(sm + SM_X);
    __nv_bfloat16* sOt = (__nv_bfloat16*)(sm + SM_X);
    __nv_bfloat16* stg = (__nv_bfloat16*)(sm + SM_X);
    float* sB1 = (float*)(sm + SM_B1);
    float* sB2 = (float*)(sm + SM_B2);

    const int tid = threadIdx.x;
    const int n   = blockIdx.x;
    const int b   = blockIdx.y / WF;
    const int wf  = blockIdx.y - b * WF;
    const int lane = tid & 31, warp = tid >> 5;
    const int g = lane >> 2, tig = lane & 3;
    const int wm = warp & 3, wq = warp >> 2;
    const int wn = wq >> 1, wh = wq & 1;

    {
        const uint4* src = (const uint4*)g_Gp;
        uint4* dst = (uint4*)sG;
        for (int p = tid; p < 128 * 136 * 2 / 16; p += 512) dst[p] = src[p];
        if (tid < 192) {
            int half = tid / 96, j = tid - half * 96;
            sB1[tid] = b1[half * (NB * BS) + n * BS + j];
            sB2[tid] = b2[half * (NB * BS) + n * BS + j];
        }
    }
    {
        const __nv_bfloat162* pa = g_A2 + ((size_t)(b * HH) * WF + wf) * CH + n * BS;
        for (int idx = tid; idx < 65 * 48; idx += 512) {
            int h = idx / 48, c = (idx - (idx / 48) * 48) * 2;
            uint2 ua = *(const uint2*)(pa + (size_t)h * WF * CH + c);
            float2 a0 = __bfloat1622float2(*(__nv_bfloat162*)&ua.x);
            float2 a1 = __bfloat1622float2(*(__nv_bfloat162*)&ua.y);
            if (h == 0 || h == 64) {
                *(__nv_bfloat162*)(sX + h * PBX + c)         = __floats2bfloat162_rn(a0.x, a1.x);
                *(__nv_bfloat162*)(sX + (128 + h) * PBX + c) = __floats2bfloat162_rn(a0.y, a1.y);
            } else {
                uint2 ub = *(const uint2*)(pa + (size_t)(128 - h) * WF * CH + c);
                float2 b0 = __bfloat1622float2(*(__nv_bfloat162*)&ub.x);
                float2 b1v = __bfloat1622float2(*(__nv_bfloat162*)&ub.y);
                *(__nv_bfloat162*)(sX + h * PBX + c) =
                    __floats2bfloat162_rn(a0.x + b0.x, a1.x + b1v.x);          // Per
                *(__nv_bfloat162*)(sX + (64 + h) * PBX + c) =
                    __floats2bfloat162_rn(a0.y - b0.y, a1.y - b1v.y);          // Mi
                *(__nv_bfloat162*)(sX + (128 + h) * PBX + c) =
                    __floats2bfloat162_rn(a0.y + b0.y, a1.y + b1v.y);          // Pei
                *(__nv_bfloat162*)(sX + (192 + h) * PBX + c) =
                    __floats2bfloat162_rn(b0.x - a0.x, b1v.x - a1.x);          // -Mr
            }
        }
    }
    __syncthreads();

    const unsigned sG_u = s2u(sG), sX_u = s2u(sX);
    const unsigned sWr_u = s2u(sWr), sWi_u = s2u(sWi);
    const unsigned abaseG = sG_u + (wm * 32) * GPP * 2 + AOFF(lane, GPP);
    const unsigned abaseX = sX_u + (wm * 32) * XP * 2 + AOFF(lane, XP);
    const unsigned bplane = sX_u + (wn * 128 * PBX + wh * 48) * 2 + BTOFF(lane, PBX);
    const unsigned boffW  = (wh * 48) * WP * 2 + BOFF(lane, WP);

    float acc[2][6][4];

    // =============== GEMM1: folded forward H-DFT (K=128) ==================
    #pragma unroll
    for (int mt = 0; mt < 2; mt++)
        #pragma unroll
        for (int nt = 0; nt < 6; nt++)
            #pragma unroll
            for (int r = 0; r < 4; r++) acc[mt][nt][r] = 0.0f;

    #pragma unroll
    for (int ks = 0; ks < 8; ks++) {
        const int k0 = ks * 16;
        unsigned a[2][4];
        ldsm_x4(a[0], abaseG + k0 * 2);
        ldsm_x4(a[1], abaseG + (16 * GPP + k0) * 2);
        #pragma unroll
        for (int nt = 0; nt < 6; nt++) {
            unsigned bb[2];
            ldsm_x2t(bb, bplane + (k0 * PBX + nt * 8) * 2);
            mma_bf16(acc[0][nt], a[0], bb[0], bb[1]);
            mma_bf16(acc[1][nt], a[1], bb[0], bb[1]);
        }
    }
    __syncthreads();

    #pragma unroll
    for (int mt = 0; mt < 2; mt++)
        #pragma unroll
        for (int nt = 0; nt < 6; nt++) {
            int row0 = wm * 32 + mt * 16 + g;
            int jj = wq * 48 + nt * 8 + 2 * tig;
            *(__nv_bfloat162*)(sXm + row0 * XP + jj) =
                __floats2bfloat162_rn(acc[mt][nt][0], acc[mt][nt][1]);
            *(__nv_bfloat162*)(sXm + (row0 + 8) * XP + jj) =
                __floats2bfloat162_rn(acc[mt][nt][2], acc[mt][nt][3]);
        }
    {
        const uint4* srcR = (const uint4*)&g_Wb[0][0][n][0];
        const uint4* srcI = (const uint4*)&g_Wb[0][1][n][0];
        uint4* dR = (uint4*)sWr;
        uint4* dI = (uint4*)sWi;
        for (int p = tid; p < 96 * 104 / 8; p += 512) { dR[p] = srcR[p]; dI[p] = srcI[p]; }
    }
    __syncthreads();

    // =============== MLP layer 1 ==========================================
    #pragma unroll
    for (int mt = 0; mt < 2; mt++)
        #pragma unroll
        for (int nt = 0; nt < 6; nt++)
            #pragma unroll
            for (int r = 0; r < 4; r++) acc[mt][nt][r] = 0.0f;

    #pragma unroll
    for (int ks = 0; ks < 12; ks++) {
        const int khalf = (ks >= 6);
        const int k0 = ks * 16, kkm = k0 - khalf * 96;
        const unsigned sW_u = (wn == 0) ? (khalf ? sWi_u : sWr_u)
                                        : (khalf ? sWr_u : sWi_u);
        const unsigned amsk = ((wn == 0) && khalf) ? 0x80008000u : 0u;
        unsigned a[2][4];
        ldsm_x4(a[0], abaseX + k0 * 2);
        ldsm_x4(a[1], abaseX + (16 * XP + k0) * 2);
        if (amsk) {
            #pragma unroll
            for (int mt = 0; mt < 2; mt++)
                #pragma unroll
                for (int r = 0; r < 4; r++) a[mt][r] ^= amsk;
        }
        #pragma unroll
        for (int nt = 0; nt < 6; nt++) {
            unsigned bb[2];
            ldsm_x2(bb, sW_u + boffW + (nt * 8 * WP + kkm) * 2);
            mma_bf16(acc[0][nt], a[0], bb[0], bb[1]);
            mma_bf16(acc[1][nt], a[1], bb[0], bb[1]);
        }
    }
    __syncthreads();

    #pragma unroll
    for (int mt = 0; mt < 2; mt++)
        #pragma unroll
        for (int nt = 0; nt < 6; nt++) {
            int row0 = wm * 32 + mt * 16 + g;
            int jj = wq * 48 + nt * 8 + 2 * tig;
            float bb0 = sB1[jj], bb1 = sB1[jj + 1];
            *(__nv_bfloat162*)(sXm + row0 * XP + jj) = __floats2bfloat162_rn(
                fmaxf(acc[mt][nt][0] + bb0, 0.0f), fmaxf(acc[mt][nt][1] + bb1, 0.0f));
            *(__nv_bfloat162*)(sXm + (row0 + 8) * XP + jj) = __floats2bfloat162_rn(
                fmaxf(acc[mt][nt][2] + bb0, 0.0f), fmaxf(acc[mt][nt][3] + bb1, 0.0f));
        }
    {
        const uint4* srcR = (const uint4*)&g_Wb[1][0][n][0];
        const uint4* srcI = (const uint4*)&g_Wb[1][1][n][0];
        uint4* dR = (uint4*)sWr;
        uint4* dI = (uint4*)sWi;
        for (int p = tid; p < 96 * 104 / 8; p += 512) { dR[p] = srcR[p]; dI[p] = srcI[p]; }
    }
    __syncthreads();

    // =============== MLP layer 2 ==========================================
    #pragma unroll
    for (int mt = 0; mt < 2; mt++)
        #pragma unroll
        for (int nt = 0; nt < 6; nt++)
            #pragma unroll
            for (int r = 0; r < 4; r++) acc[mt][nt][r] = 0.0f;

    #pragma unroll
    for (int ks = 0; ks < 12; ks++) {
        const int khalf = (ks >= 6);
        const int k0 = ks * 16, kkm = k0 - khalf * 96;
        const unsigned sW_u = (wn == 0) ? (khalf ? sWi_u : sWr_u)
                                        : (khalf ? sWr_u : sWi_u);
        const unsigned amsk = ((wn == 0) && khalf) ? 0x80008000u : 0u;
        unsigned a[2][4];
        ldsm_x4(a[0], abaseX + k0 * 2);
        ldsm_x4(a[1], abaseX + (16 * XP + k0) * 2);
        if (amsk) {
            #pragma unroll
            for (int mt = 0; mt < 2; mt++)
                #pragma unroll
                for (int r = 0; r < 4; r++) a[mt][r] ^= amsk;
        }
        #pragma unroll
        for (int nt = 0; nt < 6; nt++) {
            unsigned bb[2];
            ldsm_x2(bb, sW_u + boffW + (nt * 8 * WP + kkm) * 2);
            mma_bf16(acc[0][nt], a[0], bb[0], bb[1]);
            mma_bf16(acc[1][nt], a[1], bb[0], bb[1]);
        }
    }
    __syncthreads();

    // softshrink -> sOt natural [k-stack 256][c] ; G' reload over W
    {
        const float lam = 0.01f;
        #pragma unroll
        for (int mt = 0; mt < 2; mt++)
            #pragma unroll
            for (int nt = 0; nt < 6; nt++) {
                int row0 = wm * 32 + mt * 16 + g;
                int c = wh * 48 + nt * 8 + 2 * tig;
                int jj = wn * 96 + c;
                float bb0 = sB2[jj], bb1 = sB2[jj + 1];
                #pragma unroll
                for (int r = 0; r < 4; r++) {
                    float v = acc[mt][nt][r] + ((r & 1) ? bb1 : bb0);
                    v = copysignf(fmaxf(fabsf(v) - lam, 0.0f), v);
                    int cc = c + (r & 1);
                    int kb = wn * 128 + row0 + (r >> 1) * 8;
                    sOt[kb * PBX + cc] = __float2bfloat16_rn(v);
                }
            }
    }
    {
        const uint4* src = (const uint4*)g_Gp;
        uint4* dst = (uint4*)sG;
        for (int p = tid; p < 128 * 136 * 2 / 16; p += 512) dst[p] = src[p];
    }
    __syncthreads();

    // =============== in-place inverse fold (two-phase) ====================
    {
        unsigned rA[6], rB[6], rC[6], rD[6];
        int ns = 0;
        for (int idx = tid; idx < 63 * 48; idx += 512) {
            int m = idx / 48 + 1, c = (idx - (idx / 48) * 48) * 2;
            rA[ns] = *(unsigned*)(sOt + m * PBX + c);
            rB[ns] = *(unsigned*)(sOt + (128 - m) * PBX + c);
            rC[ns] = *(unsigned*)(sOt + (128 + m) * PBX + c);
            rD[ns] = *(unsigned*)(sOt + (256 - m) * PBX + c);
            ns++;
        }
        __syncthreads();
        ns = 0;
        for (int idx = tid; idx < 63 * 48; idx += 512) {
            int m = idx / 48 + 1, c = (idx - (idx / 48) * 48) * 2;
            float2 fa = __bfloat1622float2(*(__nv_bfloat162*)&rA[ns]);
            float2 fb = __bfloat1622float2(*(__nv_bfloat162*)&rB[ns]);
            float2 fc = __bfloat1622float2(*(__nv_bfloat162*)&rC[ns]);
            float2 fd = __bfloat1622float2(*(__nv_bfloat162*)&rD[ns]);
            *(__nv_bfloat162*)(sOt + m * PBX + c) =
                __floats2bfloat162_rn(fa.x + fb.x, fa.y + fb.y);       // POr
            *(__nv_bfloat162*)(sOt + (64 + m) * PBX + c) =
                __floats2bfloat162_rn(fd.x - fc.x, fd.y - fc.y);       // -MOi
            *(__nv_bfloat162*)(sOt + (128 + m) * PBX + c) =
                __floats2bfloat162_rn(fc.x + fd.x, fc.y + fd.y);       // POi
            *(__nv_bfloat162*)(sOt + (192 + m) * PBX + c) =
                __floats2bfloat162_rn(fa.x - fb.x, fa.y - fb.y);       // MOr
            ns++;
        }
    }
    __syncthreads();

    // =============== GEMM2: folded inverse H-DFT (K=128) ==================
    #pragma unroll
    for (int mt = 0; mt < 2; mt++)
        #pragma unroll
        for (int nt = 0; nt < 6; nt++)
            #pragma unroll
            for (int r = 0; r < 4; r++) acc[mt][nt][r] = 0.0f;

    #pragma unroll
    for (int ks = 0; ks < 8; ks++) {
        const int k0 = ks * 16;
        unsigned a[2][4];
        ldsm_x4(a[0], abaseG + k0 * 2);
        ldsm_x4(a[1], abaseG + (16 * GPP + k0) * 2);
        #pragma unroll
        for (int nt = 0; nt < 6; nt++) {
            unsigned bb[2];
            ldsm_x2t(bb, bplane + (k0 * PBX + nt * 8) * 2);
            mma_bf16(acc[0][nt], a[0], bb[0], bb[1]);
            mma_bf16(acc[1][nt], a[1], bb[0], bb[1]);
        }
    }
    __syncthreads();

    #pragma unroll
    for (int mt = 0; mt < 2; mt++)
        #pragma unroll
        for (int nt = 0; nt < 6; nt++) {
            int row0 = wm * 32 + mt * 16 + g;
            int jj = wq * 48 + nt * 8 + 2 * tig;
            *(__nv_bfloat162*)(stg + row0 * XP + jj) =
                __floats2bfloat162_rn(acc[mt][nt][0], acc[mt][nt][1]);
            *(__nv_bfloat162*)(stg + (row0 + 8) * XP + jj) =
                __floats2bfloat162_rn(acc[mt][nt][2], acc[mt][nt][3]);
        }
    __syncthreads();

    {
        __nv_bfloat162* pb = g_B2 + ((size_t)(b * HH) * WF + wf) * CH + n * BS;
        for (int idx = tid; idx < HH * BS; idx += 512) {
            int h = idx / BS, c = idx - (idx / BS) * BS;
            pb[(size_t)h * WF * CH + c] =
                __halves2bfloat162(stg[h * XP + c], stg[h * XP + 96 + c]);
        }
    }
}

// ---------------------------------------------------------------------------
// K5: W-irfft as GEMM + residual. 256 threads, 8 warps. 2 bh tiles/CTA.
// B loads via ldsm.x4.trans.
// ---------------------------------------------------------------------------
#define P5 152
#define PB5 104
#define K5_SG 0
#define K5_SB 38912
#define K5_TOT 68864

__global__ void __launch_bounds__(256) k5g(const float* __restrict__ x,
                                           float* __restrict__ out)
{
    extern __shared__ char sm[];
    __nv_bfloat16* sG = (__nv_bfloat16*)(sm + K5_SG);
    __nv_bfloat16* sB = (__nv_bfloat16*)(sm + K5_SB);

    const int tid = threadIdx.x;
    const int c0 = blockIdx.x * 96;
    const int lane = tid & 31, warp = tid >> 5;
    const int g = lane >> 2, tig = lane & 3;
    const int wm = warp & 3, wn = warp >> 2;

    {
        const unsigned* src = (const unsigned*)g_G5;
        unsigned* dst = (unsigned*)sG;
        for (int p = tid; p < 128 * 73; p += 256) {
            int row = p / 73, c = p - row * 73;
            dst[row * 76 + c] = src[p];
        }
    }
    {
        unsigned* dz = (unsigned*)sB;
        for (int p = tid; p < 144 * 52; p += 256) dz[p] = 0u;
    }

    const unsigned sG_u = s2u(sG), sB_u = s2u(sB);
    const unsigned abase   = sG_u + (wm * 32) * P5 * 2 + AOFF(lane, P5);
    const unsigned btbase4 = sB_u + AOFF(lane, PB5) + (wn * 48) * 2;

    for (int t = 0; t < 2; t++) {
        const int bh = blockIdx.y * 2 + t;
        __syncthreads();

        {
            const __nv_bfloat162* pb = g_B2 + (size_t)bh * WF * CH + c0;
            for (int idx = tid; idx < 65 * 48; idx += 256) {
                int k = idx / 48, c = (idx - (idx / 48) * 48) * 2;
                uint2 v2 = *(const uint2*)(pb + (size_t)k * CH + c);
                __nv_bfloat162 va = *(__nv_bfloat162*)&v2.x;
                __nv_bfloat162 vb = *(__nv_bfloat162*)&v2.y;
                *(__nv_bfloat162*)(sB + k * PB5 + c) =
                    __halves2bfloat162(__low2bfloat16(va), __low2bfloat16(vb));
                *(__nv_bfloat162*)(sB + (72 + k) * PB5 + c) =
                    __halves2bfloat162(__high2bfloat16(va), __high2bfloat16(vb));
            }
        }
        __syncthreads();

        float acc[2][6][4];
        #pragma unroll
        for (int mt = 0; mt < 2; mt++)
            #pragma unroll
            for (int nt = 0; nt < 6; nt++)
                #pragma unroll
                for (int r = 0; r < 4; r++) acc[mt][nt][r] = 0.0f;

        #pragma unroll
        for (int ks = 0; ks < 9; ks++) {
            const int k0 = ks * 16;
            unsigned a[2][4];
            ldsm_x4(a[0], abase + k0 * 2);
            ldsm_x4(a[1], abase + (16 * P5 + k0) * 2);
            #pragma unroll
            for (int ntp = 0; ntp < 3; ntp++) {
                unsigned bb[4];
                ldsm_x4t(bb, btbase4 + (k0 * PB5 + ntp * 16) * 2);
                mma_bf16(acc[0][2*ntp],     a[0], bb[0], bb[1]);
                mma_bf16(acc[1][2*ntp],     a[1], bb[0], bb[1]);
                mma_bf16(acc[0][2*ntp + 1], a[0], bb[2], bb[3]);
                mma_bf16(acc[1][2*ntp + 1], a[1], bb[2], bb[3]);
            }
        }

        {
            const float* px = x   + (size_t)bh * WW * CH + c0;
            float*       po = out + (size_t)bh * WW * CH + c0;
            #pragma unroll
            for (int mt = 0; mt < 2; mt++)
                #pragma unroll
                for (int nt = 0; nt < 6; nt++) {
                    int row0 = wm * 32 + mt * 16 + g;
                    int jj = wn * 48 + nt * 8 + 2 * tig;
                    float2 xv0 = *(const float2*)(px + (size_t)row0 * CH + jj);
                    float2 xv1 = *(const float2*)(px + (size_t)(row0 + 8) * CH + jj);
                    *(float2*)(po + (size_t)row0 * CH + jj) =
                        make_float2(acc[mt][nt][0] + xv0.x, acc[mt][nt][1] + xv0.y);
                    *(float2*)(po + (size_t)(row0 + 8) * CH + jj) =
                        make_float2(acc[mt][nt][2] + xv1.x, acc[mt][nt][3] + xv1.y);
                }
        }
    }
}

// ---------------------------------------------------------------------------
extern "C" void kernel_launch(void* const* d_in, const int* in_sizes, int n_in,
                              void* d_out, int out_size)
{
    (void)in_sizes; (void)n_in; (void)out_size;
    const float* x  = (const float*)d_in[0];
    const float* w1 = (const float*)d_in[1];
    const float* b1 = (const float*)d_in[2];
    const float* w2 = (const float*)d_in[3];
    const float* b2 = (const float*)d_in[4];
    float* out = (float*)d_out;

    cudaFuncSetAttribute(k1g,  cudaFuncAttributeMaxDynamicSharedMemorySize, K1_TOT);
    cudaFuncSetAttribute(kmid, cudaFuncAttributeMaxDynamicSharedMemorySize, SM_TOT);
    cudaFuncSetAttribute(k5g,  cudaFuncAttributeMaxDynamicSharedMemorySize, K5_TOT);

    k0_build<<<32, 256>>>(w1, w2);
    k1g <<<dim3(CH / 96, BB * HH / 2), 256, K1_TOT>>>(x);
    kmid<<<dim3(NB, BB * WF), 512, SM_TOT>>>(b1, b2);
    k5g <<<dim3(CH / 96, BB * HH / 2), 256, K5_TOT>>>(x, out);
}